// round 1
// baseline (speedup 1.0000x reference)
#include <cuda_runtime.h>
#include <cuda_bf16.h>
#include <stdint.h>

#define I_FEAT 4096
#define O_FEAT 11008
#define N_ROWS 4096

#define BM 128
#define BN 128
#define BK 32
#define SSTRIDE 40                  // halves per smem row (32 + 8 pad) -> conflict-free ldmatrix
#define NKT (I_FEAT / BK)           // 128 k-tiles

// ---------------- scratch (allocation-free: device globals) ----------------
__device__ __nv_bfloat16 g_W1[(size_t)O_FEAT * I_FEAT];   // hi(W)
__device__ __nv_bfloat16 g_W2[(size_t)O_FEAT * I_FEAT];   // lo(W)
__device__ __nv_bfloat16 g_X1[(size_t)N_ROWS * I_FEAT];   // hi(x)
__device__ __nv_bfloat16 g_X2[(size_t)N_ROWS * I_FEAT];   // lo(x)

// ---------------- split x into bf16 hi/lo ----------------
__global__ void split_x_kernel(const float* __restrict__ x) {
    size_t base = ((size_t)blockIdx.x * blockDim.x + threadIdx.x) * 4;
    float4 v = *reinterpret_cast<const float4*>(x + base);
    float vv[4] = {v.x, v.y, v.z, v.w};
    __nv_bfloat16 h[4], r[4];
#pragma unroll
    for (int i = 0; i < 4; ++i) {
        h[i] = __float2bfloat16(vv[i]);
        r[i] = __float2bfloat16(vv[i] - __bfloat162float(h[i]));
    }
    *reinterpret_cast<__nv_bfloat162*>(g_X1 + base)     = __halves2bfloat162(h[0], h[1]);
    *reinterpret_cast<__nv_bfloat162*>(g_X1 + base + 2) = __halves2bfloat162(h[2], h[3]);
    *reinterpret_cast<__nv_bfloat162*>(g_X2 + base)     = __halves2bfloat162(r[0], r[1]);
    *reinterpret_cast<__nv_bfloat162*>(g_X2 + base + 2) = __halves2bfloat162(r[2], r[3]);
}

// ---------------- dequantize W into bf16 hi/lo ----------------
__global__ void dequant_kernel(const int* __restrict__ idx,
                               const float* __restrict__ scales,
                               const float* __restrict__ bab) {
    size_t base = ((size_t)blockIdx.x * blockDim.x + threadIdx.x) * 4;
    int4 q = *reinterpret_cast<const int4*>(idx + base);
    size_t row = base >> 12;                 // / 4096
    int col = (int)(base & 4095);
    int blk = (int)(row << 4) + (col >> 8);  // row*16 + col/256
    float s = scales[blk] * (1.0f / 127.0f);
    float b = bab[blk];
    int qi[4] = {q.x, q.y, q.z, q.w};
    __nv_bfloat16 h[4], r[4];
#pragma unroll
    for (int i = 0; i < 4; ++i) {
        float w = (float)(qi[i] - 128) * s + b;
        h[i] = __float2bfloat16(w);
        r[i] = __float2bfloat16(w - __bfloat162float(h[i]));
    }
    *reinterpret_cast<__nv_bfloat162*>(g_W1 + base)     = __halves2bfloat162(h[0], h[1]);
    *reinterpret_cast<__nv_bfloat162*>(g_W1 + base + 2) = __halves2bfloat162(h[2], h[3]);
    *reinterpret_cast<__nv_bfloat162*>(g_W2 + base)     = __halves2bfloat162(r[0], r[1]);
    *reinterpret_cast<__nv_bfloat162*>(g_W2 + base + 2) = __halves2bfloat162(r[2], r[3]);
}

// ---------------- GEMM helpers ----------------
__device__ __forceinline__ void cp16(uint32_t dst, const void* src) {
    asm volatile("cp.async.cg.shared.global [%0], [%1], 16;\n" :: "r"(dst), "l"(src));
}
__device__ __forceinline__ void ldsm4(uint32_t& r0, uint32_t& r1, uint32_t& r2, uint32_t& r3,
                                      uint32_t addr) {
    asm volatile("ldmatrix.sync.aligned.m8n8.x4.shared.b16 {%0,%1,%2,%3}, [%4];\n"
        : "=r"(r0), "=r"(r1), "=r"(r2), "=r"(r3) : "r"(addr));
}
__device__ __forceinline__ void mma16816(float* c, const uint32_t* a, const uint32_t* b) {
    asm volatile("mma.sync.aligned.m16n8k16.row.col.f32.bf16.bf16.f32 "
        "{%0,%1,%2,%3}, {%4,%5,%6,%7}, {%8,%9}, {%0,%1,%2,%3};\n"
        : "+f"(c[0]), "+f"(c[1]), "+f"(c[2]), "+f"(c[3])
        : "r"(a[0]), "r"(a[1]), "r"(a[2]), "r"(a[3]), "r"(b[0]), "r"(b[1]));
}

// ---------------- fused 3-product split-bf16 GEMM ----------------
// out[m, o] = sum_k (X1+X2)[m,k] * (W1+W2)[o,k]  (dropping X2*W2)  + bias[o]
__global__ void __launch_bounds__(256, 2)
gemm_kernel(const float* __restrict__ bias, float* __restrict__ out) {
    extern __shared__ __align__(16) __nv_bfloat16 sm[];
    const uint32_t smbase = (uint32_t)__cvta_generic_to_shared(sm);
    constexpr int TSZ = BM * SSTRIDE;        // halves per tile  (5120)
    constexpr int STG = 4 * TSZ;             // halves per stage (A1,A2,B1,B2)

    const int m0 = (blockIdx.x & 31) * BM;   // m fastest -> W tiles shared via L2
    const int n0 = (blockIdx.x >> 5) * BN;
    const int tid = threadIdx.x;
    const int lane = tid & 31;
    const int wm = ((tid >> 5) & 1) * 64;    // warp m offset (2 warps in m)
    const int wn = (tid >> 6) * 32;          // warp n offset (4 warps in n)

    // ---- per-thread cp.async descriptors: 8 x 16B per stage ----
    const __nv_bfloat16* gbase[4] = { g_X1, g_X2, g_W1, g_W2 };
    const __nv_bfloat16* src[8];
    uint32_t dstoff[8];
    {
        const int rowa = tid >> 2;
        const int chunk = tid & 3;
#pragma unroll
        for (int t = 0; t < 8; ++t) {
            int tile = t >> 1;
            int row = rowa + (t & 1) * 64;
            int gr = (tile < 2 ? m0 : n0) + row;
            src[t] = gbase[tile] + (size_t)gr * I_FEAT + chunk * 8;
            dstoff[t] = (uint32_t)(tile * TSZ + row * SSTRIDE + chunk * 8) * 2;
        }
    }

    float acc[4][4][4];
#pragma unroll
    for (int i = 0; i < 4; ++i)
#pragma unroll
        for (int j = 0; j < 4; ++j)
#pragma unroll
            for (int k = 0; k < 4; ++k) acc[i][j][k] = 0.0f;

    // prologue: stage 0 <- k-tile 0
#pragma unroll
    for (int t = 0; t < 8; ++t) {
        cp16(smbase + dstoff[t], src[t]);
        src[t] += BK;
    }
    asm volatile("cp.async.commit_group;\n");

    for (int kt = 0; kt < NKT; ++kt) {
        const int cur = kt & 1;
        if (kt + 1 < NKT) {
            const uint32_t sb = smbase + (uint32_t)((kt + 1) & 1) * (STG * 2);
#pragma unroll
            for (int t = 0; t < 8; ++t) {
                cp16(sb + dstoff[t], src[t]);
                src[t] += BK;
            }
        }
        asm volatile("cp.async.commit_group;\n");
        asm volatile("cp.async.wait_group 1;\n");
        __syncthreads();

        const uint32_t sA1 = smbase + (uint32_t)cur * (STG * 2);
        const uint32_t sA2 = sA1 + TSZ * 2;
        const uint32_t sB1 = sA1 + 2 * TSZ * 2;
        const uint32_t sB2 = sA1 + 3 * TSZ * 2;

#pragma unroll
        for (int ks = 0; ks < 2; ++ks) {
            // B fragments: n-major tiles, k contiguous -> NON-trans ldmatrix
            uint32_t B1r[4][2], B2r[4][2];
#pragma unroll
            for (int j = 0; j < 2; ++j) {
                int brow = wn + j * 16 + (lane & 7) + ((lane >> 4) << 3);
                int bcol = ks * 16 + ((lane >> 3) & 1) * 8;
                uint32_t off = (uint32_t)(brow * SSTRIDE + bcol) * 2;
                ldsm4(B1r[j*2][0], B1r[j*2][1], B1r[j*2+1][0], B1r[j*2+1][1], sB1 + off);
                ldsm4(B2r[j*2][0], B2r[j*2][1], B2r[j*2+1][0], B2r[j*2+1][1], sB2 + off);
            }
#pragma unroll
            for (int mi = 0; mi < 4; ++mi) {
                int arow = wm + mi * 16 + (lane & 15);
                int acol = ks * 16 + ((lane >> 4) << 3);
                uint32_t off = (uint32_t)(arow * SSTRIDE + acol) * 2;
                uint32_t a1[4], a2[4];
                ldsm4(a1[0], a1[1], a1[2], a1[3], sA1 + off);
                ldsm4(a2[0], a2[1], a2[2], a2[3], sA2 + off);
#pragma unroll
                for (int ni = 0; ni < 4; ++ni) {
                    mma16816(acc[mi][ni], a1, B1r[ni]);   // x1*w1
                    mma16816(acc[mi][ni], a1, B2r[ni]);   // x1*w2
                    mma16816(acc[mi][ni], a2, B1r[ni]);   // x2*w1
                }
            }
        }
        __syncthreads();
    }

    // ---- epilogue: add bias, store fp32 ----
    const int g = lane >> 2;
    const int t4 = lane & 3;
    float2 bb[4];
#pragma unroll
    for (int ni = 0; ni < 4; ++ni) {
        int col = n0 + wn + ni * 8 + t4 * 2;
        bb[ni].x = __ldg(bias + col);
        bb[ni].y = __ldg(bias + col + 1);
    }
#pragma unroll
    for (int mi = 0; mi < 4; ++mi) {
        int row0 = m0 + wm + mi * 16 + g;
#pragma unroll
        for (int ni = 0; ni < 4; ++ni) {
            int col = n0 + wn + ni * 8 + t4 * 2;
            float2 v0 = { acc[mi][ni][0] + bb[ni].x, acc[mi][ni][1] + bb[ni].y };
            float2 v1 = { acc[mi][ni][2] + bb[ni].x, acc[mi][ni][3] + bb[ni].y };
            *reinterpret_cast<float2*>(out + (size_t)row0 * O_FEAT + col) = v0;
            *reinterpret_cast<float2*>(out + (size_t)(row0 + 8) * O_FEAT + col) = v1;
        }
    }
}

// ---------------- launch ----------------
extern "C" void kernel_launch(void* const* d_in, const int* in_sizes, int n_in,
                              void* d_out, int out_size) {
    const float* x    = (const float*)d_in[0];
    const int*   idx  = (const int*)d_in[1];
    const float* sc   = (const float*)d_in[2];
    const float* bab  = (const float*)d_in[3];
    const float* bias = (const float*)d_in[4];
    float* out = (float*)d_out;

    split_x_kernel<<<(int)(((size_t)N_ROWS * I_FEAT) / 1024), 256>>>(x);
    dequant_kernel<<<(int)(((size_t)O_FEAT * I_FEAT) / 1024), 256>>>(idx, sc, bab);

    const int smem_bytes = 2 * 4 * BM * SSTRIDE * 2;   // 81920
    cudaFuncSetAttribute(gemm_kernel, cudaFuncAttributeMaxDynamicSharedMemorySize, smem_bytes);
    gemm_kernel<<<(N_ROWS / BM) * (O_FEAT / BN), 256, smem_bytes>>>(bias, out);
}